// round 9
// baseline (speedup 1.0000x reference)
#include <cuda_runtime.h>
#include <cstdint>

#define NB     32
#define NS     577
#define NHID   768
#define NHEADS 12
#define NHD    64
#define M_TOTAL   (NB * NS)                   // 18464
#define QKV_ELEMS (NB * NHEADS * NS * NHD)    // 14,180,352

// q, k, v in [B, NH, S, HD] layout, tf32 bit patterns (Q pre-scaled by 0.125*log2e)
__device__ float g_qkv[3ull * QKV_ELEMS];
// pre-converted tf32 operands for the projection GEMM
__device__ uint32_t g_xt[(size_t)M_TOTAL * NHID];
__device__ uint32_t g_wt[3ull * NHID * NHID];

__device__ __forceinline__ uint32_t f2tf(float f) {
    uint32_t u;
    asm("cvt.rna.tf32.f32 %0, %1;" : "=r"(u) : "f"(f));
    return u;
}

__device__ __forceinline__ float ex2f(float x) {
    float y;
    asm("ex2.approx.f32 %0, %1;" : "=f"(y) : "f"(x));
    return y;
}

__device__ __forceinline__ void mma_tf32(float* d, const uint32_t* a,
                                         uint32_t b0, uint32_t b1) {
    asm volatile(
        "mma.sync.aligned.m16n8k8.row.col.f32.tf32.tf32.f32 "
        "{%0,%1,%2,%3},{%4,%5,%6,%7},{%8,%9},{%0,%1,%2,%3};"
        : "+f"(d[0]), "+f"(d[1]), "+f"(d[2]), "+f"(d[3])
        : "r"(a[0]), "r"(a[1]), "r"(a[2]), "r"(a[3]), "r"(b0), "r"(b1));
}

__device__ __forceinline__ void cpa16(uint32_t dst, const void* src, unsigned nbytes) {
    asm volatile("cp.async.cg.shared.global [%0], [%1], 16, %2;"
                 :: "r"(dst), "l"(src), "r"(nbytes));
}
#define CP_COMMIT() asm volatile("cp.async.commit_group;")
#define CP_WAIT0()  asm volatile("cp.async.wait_group 0;")

// ---------------------------------------------------------------------------
// Kernel 0: convert X and Wq/Wk/Wv to tf32 bit patterns (one pass).
// ---------------------------------------------------------------------------
#define XV  ((size_t)M_TOTAL * NHID / 4)
#define WV  ((size_t)NHID * NHID / 4)
#define CVT_TOTAL (XV + 3 * WV)

__global__ __launch_bounds__(256) void cvt_kernel(
    const float4* __restrict__ X,
    const float4* __restrict__ Wq,
    const float4* __restrict__ Wk,
    const float4* __restrict__ Wv)
{
    size_t i = (size_t)blockIdx.x * 256 + threadIdx.x;
    if (i >= CVT_TOTAL) return;
    const float4* src;
    uint4* dst;
    if (i < XV) {
        src = X + i;
        dst = (uint4*)g_xt + i;
    } else {
        size_t j = i - XV;
        int w = (int)(j / WV);
        size_t r = j % WV;
        src = (w == 0 ? Wq : w == 1 ? Wk : Wv) + r;
        dst = (uint4*)g_wt + (size_t)w * WV + r;
    }
    float4 v = *src;
    uint4 o;
    o.x = f2tf(v.x); o.y = f2tf(v.y); o.z = f2tf(v.z); o.w = f2tf(v.w);
    *dst = o;
}

// ---------------------------------------------------------------------------
// Kernel 1: fused QKV projection, tf32 MMA, cp.async double-buffered, BK=32.
// (unchanged from R6)
// ---------------------------------------------------------------------------
#define BM   128
#define BN   128
#define BK   32
#define STA  36
#define QKV_TILE   (BM * STA)
#define QKV_SMEM_U32 (4 * QKV_TILE)
#define QKV_SMEM_BYTES (QKV_SMEM_U32 * 4)

__global__ __launch_bounds__(256, 2) void qkv_proj_kernel(
    const float* __restrict__ bq,
    const float* __restrict__ bk,
    const float* __restrict__ bv,
    const float* __restrict__ lateral,
    const int*   __restrict__ mixp)
{
    extern __shared__ uint32_t smq[];
    uint32_t* Asm = smq;
    uint32_t* Bsm = smq + 2 * QKV_TILE;

    const int z = blockIdx.z;
    const float* bias = (z == 0) ? bq : (z == 1) ? bk : bv;
    const int mix = __ldg(mixp);
    const float oscale = (z == 0) ? 0.125f * 1.44269504f : 1.0f;

    const uint32_t* Xg = g_xt;
    const uint32_t* Wg = g_wt + (size_t)z * NHID * NHID;

    const int tid  = threadIdx.x;
    const int lane = tid & 31;
    const int warp = tid >> 5;
    const int g    = lane >> 2;
    const int t    = lane & 3;
    const int wm   = (warp >> 2) * 64;
    const int wn   = (warp & 3) * 32;
    const int bm   = blockIdx.x * BM;
    const int bn   = blockIdx.y * BN;

    const uint32_t smem_a = (uint32_t)__cvta_generic_to_shared(Asm);
    const uint32_t smem_b = (uint32_t)__cvta_generic_to_shared(Bsm);

    float acc[4][4][4];
    #pragma unroll
    for (int i = 0; i < 4; i++)
        #pragma unroll
        for (int j = 0; j < 4; j++)
            #pragma unroll
            for (int c = 0; c < 4; c++) acc[i][j][c] = 0.f;

    {
        #pragma unroll
        for (int it = 0; it < 4; it++) {
            int c   = tid + it * 256;
            int row = c >> 3;
            int c4  = (c & 7) * 4;
            int gm  = bm + row;
            unsigned nba = (gm < M_TOTAL) ? 16u : 0u;
            cpa16(smem_a + (row * STA + c4) * 4, Xg + (size_t)gm * NHID + c4, nba);
            cpa16(smem_b + (row * STA + c4) * 4, Wg + (size_t)(bn + row) * NHID + c4, 16u);
        }
        CP_COMMIT();
    }

    const int NKT = NHID / BK;  // 24
    for (int kt = 0; kt < NKT; kt++) {
        const int buf = kt & 1;
        CP_WAIT0();
        __syncthreads();

        if (kt + 1 < NKT) {
            const int nb = buf ^ 1;
            const int kk = (kt + 1) * BK;
            #pragma unroll
            for (int it = 0; it < 4; it++) {
                int c   = tid + it * 256;
                int row = c >> 3;
                int c4  = (c & 7) * 4;
                int gm  = bm + row;
                unsigned nba = (gm < M_TOTAL) ? 16u : 0u;
                cpa16(smem_a + (nb * QKV_TILE + row * STA + c4) * 4,
                      Xg + (size_t)gm * NHID + kk + c4, nba);
                cpa16(smem_b + (nb * QKV_TILE + row * STA + c4) * 4,
                      Wg + (size_t)(bn + row) * NHID + kk + c4, 16u);
            }
            CP_COMMIT();
        }

        const uint32_t* Ab = Asm + buf * QKV_TILE;
        const uint32_t* Bb = Bsm + buf * QKV_TILE;
        #pragma unroll
        for (int ks = 0; ks < BK; ks += 8) {
            uint32_t a[4][4], b[4][2];
            #pragma unroll
            for (int i = 0; i < 4; i++) {
                int m = wm + i * 16 + g;
                a[i][0] = Ab[m * STA + ks + t];
                a[i][1] = Ab[(m + 8) * STA + ks + t];
                a[i][2] = Ab[m * STA + ks + t + 4];
                a[i][3] = Ab[(m + 8) * STA + ks + t + 4];
            }
            #pragma unroll
            for (int j = 0; j < 4; j++) {
                int n = wn + j * 8 + g;
                b[j][0] = Bb[n * STA + ks + t];
                b[j][1] = Bb[n * STA + ks + t + 4];
            }
            #pragma unroll
            for (int i = 0; i < 4; i++)
                #pragma unroll
                for (int j = 0; j < 4; j++)
                    mma_tf32(acc[i][j], a[i], b[j][0], b[j][1]);
        }
    }

    float* dst = g_qkv + (size_t)z * QKV_ELEMS;
    #pragma unroll
    for (int i = 0; i < 4; i++) {
        int gm0 = bm + wm + i * 16 + g;
        int gm1 = gm0 + 8;
        int bb0 = gm0 / NS, ss0 = gm0 % NS;
        int bb1 = gm1 / NS, ss1 = gm1 % NS;
        #pragma unroll
        for (int j = 0; j < 4; j++) {
            int nl = bn + wn + j * 8 + 2 * t;
            int h  = nl >> 6;
            int d  = nl & 63;
            float b0 = bias[nl], b1 = bias[nl + 1];
            if (gm0 < M_TOTAL) {
                size_t i0 = (((size_t)bb0 * NHEADS + h) * NS + ss0) * NHD + d;
                float v0 = acc[i][j][0] + b0;
                float v1 = acc[i][j][1] + b1;
                if (z == mix) { v0 *= lateral[i0]; v1 *= lateral[i0 + 1]; }
                dst[i0]     = __uint_as_float(f2tf(v0 * oscale));
                dst[i0 + 1] = __uint_as_float(f2tf(v1 * oscale));
            }
            if (gm1 < M_TOTAL) {
                size_t i1 = (((size_t)bb1 * NHEADS + h) * NS + ss1) * NHD + d;
                float v2 = acc[i][j][2] + b0;
                float v3 = acc[i][j][3] + b1;
                if (z == mix) { v2 *= lateral[i1]; v3 *= lateral[i1 + 1]; }
                dst[i1]     = __uint_as_float(f2tf(v2 * oscale));
                dst[i1 + 1] = __uint_as_float(f2tf(v3 * oscale));
            }
        }
    }
}

// ---------------------------------------------------------------------------
// Kernel 2: flash attention, tf32 MMA, max-free softmax, IN-REGISTER exp:
// the S-computing warp exponentiates + tf32-converts its fragment and stores
// finished P directly. 2 syncs/chunk. Row sums in registers, one end merge.
// ---------------------------------------------------------------------------
#define BQ2  64
#define QT2  10
#define NCH  10
#define KST  68
#define VST  72

#define OF_K   0
#define OF_V   (2 * 64 * KST)
#define OF_P   (OF_V + 2 * 64 * VST)
#define OF_L   (OF_P + 64 * KST)
#define SMEM_FLOATS (OF_L + 64)
#define SMEM_BYTES  (SMEM_FLOATS * 4)

__global__ __launch_bounds__(512, 2) void attn_kernel(float* __restrict__ out)
{
    extern __shared__ float smem[];
    float*    Ps  = smem + OF_P;
    uint32_t* Pu  = (uint32_t*)Ps;
    float*    row_l = smem + OF_L;
    const uint32_t smem_u32 = (uint32_t)__cvta_generic_to_shared(smem);

    const int tid  = threadIdx.x;
    const int lane = tid & 31;
    const int warp = tid >> 5;
    const int g    = lane >> 2;
    const int t    = lane & 3;
    const int mi   = warp >> 2;
    const int ni   = warp & 3;

    const int bh = blockIdx.x / QT2;
    const int qt = blockIdx.x % QT2;
    const int q0 = qt * BQ2;
    const int bb = bh / NHEADS;
    const int hh = bh % NHEADS;

    const uint32_t* qptr = (const uint32_t*)g_qkv + (size_t)bh * NS * NHD;
    const uint32_t* kptr = (const uint32_t*)g_qkv + (size_t)QKV_ELEMS + (size_t)bh * NS * NHD;
    const uint32_t* vptr = (const uint32_t*)g_qkv + (size_t)2 * QKV_ELEMS + (size_t)bh * NS * NHD;

    const int row0 = tid >> 4;
    const int c4   = (tid & 15) * 4;

    #pragma unroll
    for (int it = 0; it < 2; it++) {
        int row = row0 + it * 32;
        cpa16(smem_u32 + (OF_K + row * KST + c4) * 4, kptr + (size_t)row * NHD + c4, 16u);
        cpa16(smem_u32 + (OF_V + row * VST + c4) * 4, vptr + (size_t)row * NHD + c4, 16u);
    }
    CP_COMMIT();

    #pragma unroll
    for (int it = 0; it < 2; it++) {
        int row = row0 + it * 32;
        int s   = q0 + row;
        uint4 v = (s < NS) ? *(const uint4*)(qptr + (size_t)s * NHD + c4)
                           : make_uint4(0u, 0u, 0u, 0u);
        *(uint4*)((uint32_t*)Ps + row * KST + c4) = v;
    }
    if (tid < 64) row_l[tid] = 0.f;
    __syncthreads();

    uint32_t aq[8][4];
    {
        int r0 = (mi * 16 + g) * KST;
        int r1 = r0 + 8 * KST;
        #pragma unroll
        for (int ks = 0; ks < 8; ks++) {
            aq[ks][0] = Pu[r0 + ks * 8 + t];
            aq[ks][1] = Pu[r1 + ks * 8 + t];
            aq[ks][2] = Pu[r0 + ks * 8 + t + 4];
            aq[ks][3] = Pu[r1 + ks * 8 + t + 4];
        }
    }

    // per-thread exp-sum partials for rows mi*16+g and mi*16+8+g (cols this
    // thread produced in the S fragments, summed over all chunks)
    float lp0 = 0.f, lp1 = 0.f;

    float accO[2][4];
    #pragma unroll
    for (int j = 0; j < 2; j++)
        #pragma unroll
        for (int c = 0; c < 4; c++) accO[j][c] = 0.f;

    const int pr0 = (mi * 16 + g) * KST;
    const int pr1 = pr0 + 8 * KST;

    for (int kt = 0; kt < NCH; kt++) {
        const int buf = kt & 1;
        const uint32_t* kb = (uint32_t*)smem + OF_K + buf * 64 * KST;
        const uint32_t* vb = (uint32_t*)smem + OF_V + buf * 64 * VST;

        CP_WAIT0();
        __syncthreads();   // buffers ready; all PV reads of previous P done

        if (kt + 1 < NCH) {
            const int kofs = OF_K + (buf ^ 1) * 64 * KST;
            const int vofs = OF_V + (buf ^ 1) * 64 * VST;
            #pragma unroll
            for (int it = 0; it < 2; it++) {
                int row = row0 + it * 32;
                int gk  = (kt + 1) * 64 + row;
                unsigned nb = (gk < NS) ? 16u : 0u;
                cpa16(smem_u32 + (kofs + row * KST + c4) * 4, kptr + (size_t)gk * NHD + c4, nb);
                cpa16(smem_u32 + (vofs + row * VST + c4) * 4, vptr + (size_t)gk * NHD + c4, nb);
            }
            CP_COMMIT();
        }

        // ---- S = Q @ K_chunk^T (log2-domain scores) ----
        float sacc[2][4];
        #pragma unroll
        for (int j = 0; j < 2; j++)
            #pragma unroll
            for (int c = 0; c < 4; c++) sacc[j][c] = 0.f;

        #pragma unroll
        for (int ks = 0; ks < 8; ks++) {
            #pragma unroll
            for (int j = 0; j < 2; j++) {
                int nr = (ni * 16 + j * 8 + g) * KST + ks * 8;
                mma_tf32(sacc[j], aq[ks], kb[nr + t], kb[nr + t + 4]);
            }
        }

        // ---- in-register exp2 + tf32 convert + row-sum accumulate ----
        #pragma unroll
        for (int j = 0; j < 2; j++) {
            int cl = ni * 16 + j * 8 + 2 * t;        // col within chunk
            int gk = kt * 64 + cl;                   // global key index
            bool v0 = gk < NS, v1 = gk + 1 < NS;
            float e00 = v0 ? ex2f(sacc[j][0]) : 0.f;
            float e01 = v1 ? ex2f(sacc[j][1]) : 0.f;
            float e10 = v0 ? ex2f(sacc[j][2]) : 0.f;
            float e11 = v1 ? ex2f(sacc[j][3]) : 0.f;
            lp0 += e00 + e01;
            lp1 += e10 + e11;
            uint2 u0 = make_uint2(f2tf(e00), f2tf(e01));
            uint2 u1 = make_uint2(f2tf(e10), f2tf(e11));
            *(uint2*)&Pu[pr0 + cl] = u0;
            *(uint2*)&Pu[pr1 + cl] = u1;
        }
        __syncthreads();   // P complete for all ni warps of each mi band

        // ---- O += P_chunk @ V_chunk ----
        const int nks = (kt == NCH - 1) ? 1 : 8;
        for (int ks = 0; ks < nks; ks++) {
            uint32_t a[4];
            a[0] = Pu[pr0 + ks * 8 + t];
            a[1] = Pu[pr1 + ks * 8 + t];
            a[2] = Pu[pr0 + ks * 8 + t + 4];
            a[3] = Pu[pr1 + ks * 8 + t + 4];
            #pragma unroll
            for (int j = 0; j < 2; j++) {
                int nc = ni * 16 + j * 8 + g;
                mma_tf32(accO[j], a, vb[(ks * 8 + t) * VST + nc],
                                     vb[(ks * 8 + t + 4) * VST + nc]);
            }
        }
    }

    // ---- merge row sums: reduce over quad lanes (t), then across ni warps ----
    lp0 += __shfl_xor_sync(0xffffffffu, lp0, 1);
    lp0 += __shfl_xor_sync(0xffffffffu, lp0, 2);
    lp1 += __shfl_xor_sync(0xffffffffu, lp1, 1);
    lp1 += __shfl_xor_sync(0xffffffffu, lp1, 2);
    if (t == 0) {
        atomicAdd(&row_l[mi * 16 + g],     lp0);
        atomicAdd(&row_l[mi * 16 + 8 + g], lp1);
    }
    __syncthreads();

    const float inva = 1.f / row_l[mi * 16 + g];
    const float invb = 1.f / row_l[mi * 16 + 8 + g];
    #pragma unroll
    for (int j = 0; j < 2; j++) {
        int dc = hh * NHD + ni * 16 + j * 8 + 2 * t;
        int s0 = q0 + mi * 16 + g;
        int s1 = s0 + 8;
        if (s0 < NS) {
            size_t base = ((size_t)bb * NS + s0) * NHID + dc;
            out[base]     = accO[j][0] * inva;
            out[base + 1] = accO[j][1] * inva;
        }
        if (s1 < NS) {
            size_t base = ((size_t)bb * NS + s1) * NHID + dc;
            out[base]     = accO[j][2] * invb;
            out[base + 1] = accO[j][3] * invb;
        }
    }
}

// ---------------------------------------------------------------------------
extern "C" void kernel_launch(void* const* d_in, const int* in_sizes, int n_in,
                              void* d_out, int out_size)
{
    const float* hs  = (const float*)d_in[0];
    const float* lat = (const float*)d_in[1];
    const float* Wq  = (const float*)d_in[2];
    const float* bq  = (const float*)d_in[3];
    const float* Wk  = (const float*)d_in[4];
    const float* bk  = (const float*)d_in[5];
    const float* Wv  = (const float*)d_in[6];
    const float* bv  = (const float*)d_in[7];
    const int*   mix = (const int*)d_in[8];
    float* out = (float*)d_out;

    int cvt_blocks = (int)((CVT_TOTAL + 255) / 256);
    cvt_kernel<<<cvt_blocks, 256>>>((const float4*)hs, (const float4*)Wq,
                                    (const float4*)Wk, (const float4*)Wv);

    cudaFuncSetAttribute(qkv_proj_kernel, cudaFuncAttributeMaxDynamicSharedMemorySize,
                         (int)QKV_SMEM_BYTES);
    dim3 g1((M_TOTAL + BM - 1) / BM, NHID / BN, 3);
    qkv_proj_kernel<<<g1, 256, QKV_SMEM_BYTES>>>(bq, bk, bv, lat, mix);

    cudaFuncSetAttribute(attn_kernel, cudaFuncAttributeMaxDynamicSharedMemorySize,
                         (int)SMEM_BYTES);
    attn_kernel<<<NB * NHEADS * QT2, 512, SMEM_BYTES>>>(out);
}